// round 15
// baseline (speedup 1.0000x reference)
#include <cuda_runtime.h>
#include <cuda_bf16.h>
#include <cstdint>
#include <cstring>

// Problem constants
#define Bz   4
#define Nseq 2048
#define Cdim 1024
#define Hn   16
#define Dh   64
#define BHn  (Bz * Hn)

// Scratch (device globals; referenced ONLY inside device code).
// q/k/v bf16 hi/lo splits, [bh][n][d]; q pre-scaled by 0.125
__device__ __nv_bfloat16 g_qh[(size_t)BHn * Nseq * Dh];
__device__ __nv_bfloat16 g_ql[(size_t)BHn * Nseq * Dh];
__device__ __nv_bfloat16 g_kh[(size_t)BHn * Nseq * Dh];
__device__ __nv_bfloat16 g_kl[(size_t)BHn * Nseq * Dh];
__device__ __nv_bfloat16 g_vh[(size_t)BHn * Nseq * Dh];
__device__ __nv_bfloat16 g_vl[(size_t)BHn * Nseq * Dh];
// Activations pre-split to bf16 hi/lo ([M][1024] row-major)
__device__ __nv_bfloat16 g_xh[(size_t)Bz * Nseq * Cdim];
__device__ __nv_bfloat16 g_xl[(size_t)Bz * Nseq * Cdim];
__device__ __nv_bfloat16 g_yh[(size_t)Bz * Nseq * Cdim];
__device__ __nv_bfloat16 g_yl[(size_t)Bz * Nseq * Cdim];
// Pre-transposed + bf16-split weights: [F][K=1024] layout, K contiguous
__device__ __nv_bfloat16 g_w1t_hi[(size_t)3 * Cdim * Cdim];
__device__ __nv_bfloat16 g_w1t_lo[(size_t)3 * Cdim * Cdim];
__device__ __nv_bfloat16 g_w2t_hi[(size_t)Cdim * Cdim];
__device__ __nv_bfloat16 g_w2t_lo[(size_t)Cdim * Cdim];

// ---------------------------------------------------------------------------
// Warp-MMA helpers (base PTX)
// ---------------------------------------------------------------------------
__device__ __forceinline__ uint32_t smem_u32(const void* p) {
    uint32_t a;
    asm("{ .reg .u64 t; cvta.to.shared.u64 t, %1; cvt.u32.u64 %0, t; }" : "=r"(a) : "l"(p));
    return a;
}
__device__ __forceinline__ void ldsm4(uint32_t* r, uint32_t addr) {
    asm volatile("ldmatrix.sync.aligned.m8n8.x4.shared.b16 {%0,%1,%2,%3}, [%4];"
                 : "=r"(r[0]), "=r"(r[1]), "=r"(r[2]), "=r"(r[3]) : "r"(addr));
}
__device__ __forceinline__ void ldsm4t(uint32_t* r, uint32_t addr) {
    asm volatile("ldmatrix.sync.aligned.m8n8.x4.trans.shared.b16 {%0,%1,%2,%3}, [%4];"
                 : "=r"(r[0]), "=r"(r[1]), "=r"(r[2]), "=r"(r[3]) : "r"(addr));
}
__device__ __forceinline__ void mma16816(float* c, const uint32_t* a, const uint32_t* b) {
    asm volatile(
        "mma.sync.aligned.m16n8k16.row.col.f32.bf16.bf16.f32 "
        "{%0,%1,%2,%3}, {%4,%5,%6,%7}, {%8,%9}, {%0,%1,%2,%3};"
        : "+f"(c[0]), "+f"(c[1]), "+f"(c[2]), "+f"(c[3])
        : "r"(a[0]), "r"(a[1]), "r"(a[2]), "r"(a[3]), "r"(b[0]), "r"(b[1]));
}
__device__ __forceinline__ void cpa16(uint32_t daddr, const void* g) {
    asm volatile("cp.async.cg.shared.global [%0], [%1], 16;" :: "r"(daddr), "l"(g));
}
__device__ __forceinline__ void cpa_commit() { asm volatile("cp.async.commit_group;"); }
template <int N> __device__ __forceinline__ void cpa_wait() {
    asm volatile("cp.async.wait_group %0;" :: "n"(N));
}
__device__ __forceinline__ uint32_t pack2(float a, float b) {
    __nv_bfloat162 t;
    t.x = __float2bfloat16_rn(a); t.y = __float2bfloat16_rn(b);
    uint32_t u; memcpy(&u, &t, 4); return u;
}

// ---------------------------------------------------------------------------
// Weight pre-pass: w [K=1024, F] fp32 -> hi/lo [F, 1024] bf16 (split transpose)
// ---------------------------------------------------------------------------
template <int W>
__global__ __launch_bounds__(256)
void split_transpose(const float* __restrict__ w, int F)
{
    __nv_bfloat16* hi = (W == 0) ? g_w1t_hi : g_w2t_hi;
    __nv_bfloat16* lo = (W == 0) ? g_w1t_lo : g_w2t_lo;
    __shared__ float t[32][33];
    const int f0 = blockIdx.x * 32, k0 = blockIdx.y * 32;
    const int x = threadIdx.x, y0 = threadIdx.y;
#pragma unroll
    for (int r = 0; r < 4; r++) {
        int ky = y0 + r * 8;
        t[ky][x] = w[(size_t)(k0 + ky) * F + f0 + x];
    }
    __syncthreads();
#pragma unroll
    for (int r = 0; r < 4; r++) {
        int fy = y0 + r * 8;
        float v = t[x][fy];
        __nv_bfloat16 h = __float2bfloat16_rn(v);
        __nv_bfloat16 l = __float2bfloat16_rn(v - __bfloat162float(h));
        size_t o = (size_t)(f0 + fy) * 1024 + k0 + x;
        hi[o] = h; lo[o] = l;
    }
}

// ---------------------------------------------------------------------------
// Activation pre-pass: x fp32 -> g_xh/g_xl bf16 (no transpose, 4 elems/thread)
// ---------------------------------------------------------------------------
__global__ __launch_bounds__(256)
void split_act(const float* __restrict__ x)
{
    size_t i4 = ((size_t)blockIdx.x * 256 + threadIdx.x) * 4;
    float4 v = *(const float4*)(x + i4);
    __nv_bfloat16 hx = __float2bfloat16_rn(v.x);
    __nv_bfloat16 hy = __float2bfloat16_rn(v.y);
    __nv_bfloat16 hz = __float2bfloat16_rn(v.z);
    __nv_bfloat16 hw = __float2bfloat16_rn(v.w);
    uint2 hh, ll;
    __nv_bfloat162 h01; h01.x = hx; h01.y = hy;
    __nv_bfloat162 h23; h23.x = hz; h23.y = hw;
    memcpy(&hh.x, &h01, 4); memcpy(&hh.y, &h23, 4);
    ll.x = pack2(v.x - __bfloat162float(hx), v.y - __bfloat162float(hy));
    ll.y = pack2(v.z - __bfloat162float(hz), v.w - __bfloat162float(hw));
    *(uint2*)(g_xh + i4) = hh;
    *(uint2*)(g_xl + i4) = ll;
}

// ---------------------------------------------------------------------------
// mma.sync GEMM, all-bf16 inputs (pre-split), BK=16, THREE-stage cp.async
// pipeline (dynamic smem 72KB, opt-in), one barrier per k-chunk.
// Invariant at top of iter kt: pending groups = {kt, kt+1} (only {kt} on the
// last iter). wait<1> drains kt (wait<0> on last). The barrier publishes
// B[kt%3] AND proves all threads finished iter kt-1's ldsm of B[(kt-1)%3];
// issue(kt+2) writes buffer (kt+2)%3 == (kt-1)%3 — exactly the proven-free
// one — and now has ~2 full iterations to land before its wait.
// MODE 0: A = g_xh/l, B = g_w1t -> scatter q/k/v bf16 hi/lo (q scaled 0.125)
// MODE 1: A = g_yh/l, B = g_w2t -> row-major fp32 Cout
// ---------------------------------------------------------------------------
#define BK2    16
#define ASTR2  24                       // b16 row stride (48B): banks 0,3,6,1,4,7,2,5
#define ARR_B  (128 * ASTR2 * 2)        // 6144 B per array
#define OFF2_AH 0
#define OFF2_AL (1 * ARR_B)
#define OFF2_BH (2 * ARR_B)
#define OFF2_BL (3 * ARR_B)
#define BUF2   (4 * ARR_B)              // 24576 B per stage
#define NSTG   3
#define GSMEM  (NSTG * BUF2)            // 73728 B (dynamic, opt-in)
#define NKC2   (1024 / BK2)             // 64 chunks

template <int MODE>
__global__ __launch_bounds__(256, 2)
void mma_gemm(float* __restrict__ Cout)
{
    extern __shared__ __align__(128) char smem[];
    const uint32_t sbase = smem_u32(smem);
    const int tid  = threadIdx.x;
    const int wid  = tid >> 5, lane = tid & 31;
    const int wm   = wid >> 2;
    const int wn   = wid & 3;
    const int bM   = blockIdx.y * 128, bN = blockIdx.x * 128;

    const __nv_bfloat16* Ah = ((MODE == 0) ? g_xh : g_yh) + (size_t)bM * 1024;
    const __nv_bfloat16* Al = ((MODE == 0) ? g_xl : g_yl) + (size_t)bM * 1024;
    const __nv_bfloat16* Bh = ((MODE == 0) ? g_w1t_hi : g_w2t_hi) + (size_t)bN * 1024;
    const __nv_bfloat16* Bl = ((MODE == 0) ? g_w1t_lo : g_w2t_lo) + (size_t)bN * 1024;

    float acc[4][4][4];
#pragma unroll
    for (int i = 0; i < 4; i++)
#pragma unroll
        for (int j = 0; j < 4; j++)
#pragma unroll
            for (int r = 0; r < 4; r++) acc[i][j][r] = 0.f;

    // cp.async: thread e loads row r=e>>1, half h=e&1 (16B) per array.
    const int ldR = tid >> 1, ldH = tid & 1;
    auto issue = [&](int kt, int b) {
        uint32_t dbase = sbase + b * BUF2;
        uint32_t doff = (uint32_t)(ldR * ASTR2 + ldH * 8) * 2;
        size_t goff = (size_t)ldR * 1024 + kt * BK2 + ldH * 8;
        cpa16(dbase + OFF2_AH + doff, Ah + goff);
        cpa16(dbase + OFF2_AL + doff, Al + goff);
        cpa16(dbase + OFF2_BH + doff, Bh + goff);
        cpa16(dbase + OFF2_BL + doff, Bl + goff);
        cpa_commit();
    };

    const uint32_t aRow = wm * 64 + (lane & 15);
    const uint32_t aCol = (uint32_t)(lane >> 4) << 3;
    const uint32_t bRow = wn * 32 + (((uint32_t)(lane >> 4)) << 3) + (lane & 7);
    const uint32_t bCol = (((uint32_t)(lane >> 3)) & 1) << 3;

    // Prologue: two chunks in flight.
    issue(0, 0);
    issue(1, 1);
    for (int kt = 0; kt < NKC2; kt++) {
        const int b = kt % NSTG;
        if (kt + 1 < NKC2) cpa_wait<1>();   // pending {kt, kt+1} -> drain kt
        else               cpa_wait<0>();   // pending {kt} only -> drain it
        __syncthreads();                    // publish stage b; ldsm of (kt-1)%3 done

        if (kt + 2 < NKC2) issue(kt + 2, (kt + 2) % NSTG);  // == (kt-1)%3, proven free

        // ---- ldsm ALL fragments for stage b into registers ----
        const uint32_t base = sbase + b * BUF2;
        uint32_t ah[4][4], al[4][4], bh[4][2], bl[4][2];
#pragma unroll
        for (int mt = 0; mt < 4; mt++) {
            uint32_t off = ((aRow + mt * 16) * ASTR2 + aCol) * 2;
            ldsm4(ah[mt], base + OFF2_AH + off);
            ldsm4(al[mt], base + OFF2_AL + off);
        }
#pragma unroll
        for (int g = 0; g < 2; g++) {
            uint32_t off = ((bRow + g * 16) * ASTR2 + bCol) * 2;
            uint32_t t[4];
            ldsm4(t, base + OFF2_BH + off);
            bh[g * 2][0] = t[0]; bh[g * 2][1] = t[1];
            bh[g * 2 + 1][0] = t[2]; bh[g * 2 + 1][1] = t[3];
            ldsm4(t, base + OFF2_BL + off);
            bl[g * 2][0] = t[0]; bl[g * 2][1] = t[1];
            bl[g * 2 + 1][0] = t[2]; bl[g * 2 + 1][1] = t[3];
        }

#pragma unroll
        for (int mt = 0; mt < 4; mt++)
#pragma unroll
            for (int nt = 0; nt < 4; nt++) {
                mma16816(acc[mt][nt], ah[mt], bh[nt]);
                mma16816(acc[mt][nt], ah[mt], bl[nt]);
                mma16816(acc[mt][nt], al[mt], bh[nt]);
            }
    }

    const int rq = lane >> 2, cq = (lane & 3) * 2;
#pragma unroll
    for (int mt = 0; mt < 4; mt++) {
        int m0 = bM + wm * 64 + mt * 16 + rq;
#pragma unroll
        for (int nt = 0; nt < 4; nt++) {
            int f = bN + wn * 32 + nt * 8 + cq;
            if (MODE == 0) {
                int sec = f >> 10, cc = f & (Cdim - 1);
                int h = cc >> 6, d = cc & 63;
                __nv_bfloat16* dhp = (sec == 0) ? g_qh : (sec == 1) ? g_kh : g_vh;
                __nv_bfloat16* dlp = (sec == 0) ? g_ql : (sec == 1) ? g_kl : g_vl;
                float scale = (sec == 0) ? 0.125f : 1.0f;
#pragma unroll
                for (int half = 0; half < 2; half++) {
                    int m = m0 + half * 8;
                    float v0 = acc[mt][nt][half * 2] * scale;
                    float v1 = acc[mt][nt][half * 2 + 1] * scale;
                    __nv_bfloat16 h0 = __float2bfloat16_rn(v0);
                    __nv_bfloat16 h1 = __float2bfloat16_rn(v1);
                    size_t idx = (((size_t)(m >> 11) * Hn + h) * Nseq + (m & (Nseq - 1))) * Dh + d;
                    __nv_bfloat162 hp; hp.x = h0; hp.y = h1;
                    uint32_t hw; memcpy(&hw, &hp, 4);
                    *(uint32_t*)&dhp[idx] = hw;
                    *(uint32_t*)&dlp[idx] = pack2(v0 - __bfloat162float(h0),
                                                  v1 - __bfloat162float(h1));
                }
            } else {
#pragma unroll
                for (int half = 0; half < 2; half++) {
                    int m = m0 + half * 8;
                    float* p = Cout + (size_t)m * Cdim + f;
                    *(float2*)p = make_float2(acc[mt][nt][half * 2], acc[mt][nt][half * 2 + 1]);
                }
            }
        }
    }
}

// ---------------------------------------------------------------------------
// Flash attention via mma.sync (verified R8-R14, unchanged this round).
// Pipeline order here is the PROVEN one: issue(next) BEFORE cpa_wait<1>.
// ---------------------------------------------------------------------------
#define AKT   32
#define ANT   (Nseq / AKT)
#define DSTR  72
#define ATILE (AKT * DSTR * 2)
#define ABUF  (4 * ATILE)

__global__ __launch_bounds__(128, 4)
void attn_mma()
{
    __shared__ __align__(128) char smem[2 * ABUF];
    const uint32_t sbase = smem_u32(smem);
    const int tid = threadIdx.x, lane = tid & 31, wid = tid >> 5;
    const int bh = blockIdx.y, q0 = blockIdx.x * 64;

    const __nv_bfloat16* Qhp = g_qh + ((size_t)bh * Nseq + q0) * Dh;
    const __nv_bfloat16* Qlp = g_ql + ((size_t)bh * Nseq + q0) * Dh;
    const __nv_bfloat16* Khp = g_kh + (size_t)bh * Nseq * Dh;
    const __nv_bfloat16* Klp = g_kl + (size_t)bh * Nseq * Dh;
    const __nv_bfloat16* Vhp = g_vh + (size_t)bh * Nseq * Dh;
    const __nv_bfloat16* Vlp = g_vl + (size_t)bh * Nseq * Dh;

#pragma unroll
    for (int i = 0; i < 4; i++) {
        int e = tid + i * 128;
        int r = e >> 3, c8 = e & 7;
        *(uint4*)(smem + r * (DSTR * 2) + c8 * 16) =
            *(const uint4*)(Qhp + (size_t)r * Dh + c8 * 8);
        *(uint4*)(smem + ABUF + r * (DSTR * 2) + c8 * 16) =
            *(const uint4*)(Qlp + (size_t)r * Dh + c8 * 8);
    }
    __syncthreads();

    uint32_t qh[4][4], ql[4][4];
    {
        uint32_t row = wid * 16 + (lane & 15);
        uint32_t col = ((uint32_t)(lane >> 4) & 1) << 3;
#pragma unroll
        for (int kc = 0; kc < 4; kc++) {
            uint32_t off = (row * DSTR + kc * 16 + col) * 2;
            ldsm4(qh[kc], sbase + off);
            ldsm4(ql[kc], sbase + ABUF + off);
        }
    }
    __syncthreads();

    float m0 = -1e30f, m1 = -1e30f, l0 = 0.f, l1 = 0.f;
    float y[8][4];
#pragma unroll
    for (int i = 0; i < 8; i++)
#pragma unroll
        for (int j = 0; j < 4; j++) y[i][j] = 0.f;

    auto issue = [&](int t, int b) {
        uint32_t dbase = sbase + b * ABUF;
        const __nv_bfloat16* kh = Khp + (size_t)t * AKT * Dh;
        const __nv_bfloat16* kl = Klp + (size_t)t * AKT * Dh;
        const __nv_bfloat16* vh = Vhp + (size_t)t * AKT * Dh;
        const __nv_bfloat16* vl = Vlp + (size_t)t * AKT * Dh;
#pragma unroll
        for (int i = 0; i < 2; i++) {
            int e = tid + i * 128;
            int r = e >> 3, c8 = e & 7;
            uint32_t doff = r * (DSTR * 2) + c8 * 16;
            size_t goff = (size_t)r * Dh + c8 * 8;
            cpa16(dbase + 0 * ATILE + doff, kh + goff);
            cpa16(dbase + 1 * ATILE + doff, kl + goff);
            cpa16(dbase + 2 * ATILE + doff, vh + goff);
            cpa16(dbase + 3 * ATILE + doff, vl + goff);
        }
        cpa_commit();
    };

    issue(0, 0);
    for (int t = 0; t < ANT; t++) {
        const int b = t & 1;
        if (t + 1 < ANT) { issue(t + 1, b ^ 1); cpa_wait<1>(); }
        else             { cpa_wait<0>(); }
        __syncthreads();

        const uint32_t kb = sbase + b * ABUF;

        float s[4][4];
#pragma unroll
        for (int i = 0; i < 4; i++)
#pragma unroll
            for (int j = 0; j < 4; j++) s[i][j] = 0.f;
        {
            uint32_t brow = (((uint32_t)(lane >> 4)) << 3) + (lane & 7);
            uint32_t bcol = (((uint32_t)(lane >> 3)) & 1) << 3;
#pragma unroll
            for (int kc = 0; kc < 4; kc++) {
                uint32_t kfh[8], kfl[8];
#pragma unroll
                for (int kg = 0; kg < 2; kg++) {
                    uint32_t off = ((brow + kg * 16) * DSTR + kc * 16 + bcol) * 2;
                    ldsm4(kfh + kg * 4, kb + 0 * ATILE + off);
                    ldsm4(kfl + kg * 4, kb + 1 * ATILE + off);
                }
#pragma unroll
                for (int nt = 0; nt < 4; nt++) {
                    uint32_t bhf[2] = {kfh[nt * 2], kfh[nt * 2 + 1]};
                    uint32_t blf[2] = {kfl[nt * 2], kfl[nt * 2 + 1]};
                    mma16816(s[nt], qh[kc], bhf);
                    mma16816(s[nt], qh[kc], blf);
                    mma16816(s[nt], ql[kc], bhf);
                }
            }
        }

        float mx0 = s[0][0], mx1 = s[0][2];
#pragma unroll
        for (int nt = 0; nt < 4; nt++) {
            mx0 = fmaxf(mx0, fmaxf(s[nt][0], s[nt][1]));
            mx1 = fmaxf(mx1, fmaxf(s[nt][2], s[nt][3]));
        }
#pragma unroll
        for (int off = 1; off <= 2; off <<= 1) {
            mx0 = fmaxf(mx0, __shfl_xor_sync(0xffffffffu, mx0, off));
            mx1 = fmaxf(mx1, __shfl_xor_sync(0xffffffffu, mx1, off));
        }
        float mn0 = fmaxf(m0, mx0), mn1 = fmaxf(m1, mx1);
        float al0 = __expf(m0 - mn0), al1 = __expf(m1 - mn1);
        m0 = mn0; m1 = mn1;

        float ls0 = 0.f, ls1 = 0.f;
#pragma unroll
        for (int nt = 0; nt < 4; nt++) {
            s[nt][0] = __expf(s[nt][0] - mn0);
            s[nt][1] = __expf(s[nt][1] - mn0);
            s[nt][2] = __expf(s[nt][2] - mn1);
            s[nt][3] = __expf(s[nt][3] - mn1);
            ls0 += s[nt][0] + s[nt][1];
            ls1 += s[nt][2] + s[nt][3];
        }
#pragma unroll
        for (int off = 1; off <= 2; off <<= 1) {
            ls0 += __shfl_xor_sync(0xffffffffu, ls0, off);
            ls1 += __shfl_xor_sync(0xffffffffu, ls1, off);
        }
        l0 = l0 * al0 + ls0;
        l1 = l1 * al1 + ls1;
#pragma unroll
        for (int dt = 0; dt < 8; dt++) {
            y[dt][0] *= al0; y[dt][1] *= al0;
            y[dt][2] *= al1; y[dt][3] *= al1;
        }

        uint32_t pah[2][4], pal[2][4];
#pragma unroll
        for (int kc = 0; kc < 2; kc++) {
#pragma unroll
            for (int q = 0; q < 4; q++) {
                int nt = 2 * kc + (q >> 1);
                int j0 = (q & 1) * 2;
                float p0 = s[nt][j0], p1 = s[nt][j0 + 1];
                __nv_bfloat16 h0 = __float2bfloat16_rn(p0);
                __nv_bfloat16 h1 = __float2bfloat16_rn(p1);
                __nv_bfloat162 hp; hp.x = h0; hp.y = h1;
                memcpy(&pah[kc][q], &hp, 4);
                pal[kc][q] = pack2(p0 - __bfloat162float(h0), p1 - __bfloat162float(h1));
            }
        }

        {
            uint32_t vrow = lane & 15;
            uint32_t vcol = ((uint32_t)(lane >> 4) & 1) << 3;
#pragma unroll
            for (int kc = 0; kc < 2; kc++) {
#pragma unroll
                for (int dg = 0; dg < 4; dg++) {
                    uint32_t off = ((kc * 16 + vrow) * DSTR + dg * 16 + vcol) * 2;
                    uint32_t vfh[4], vfl[4];
                    ldsm4t(vfh, kb + 2 * ATILE + off);
                    ldsm4t(vfl, kb + 3 * ATILE + off);
                    uint32_t b0h[2] = {vfh[0], vfh[1]}, b1h[2] = {vfh[2], vfh[3]};
                    uint32_t b0l[2] = {vfl[0], vfl[1]}, b1l[2] = {vfl[2], vfl[3]};
                    mma16816(y[dg * 2],     pah[kc], b0h);
                    mma16816(y[dg * 2],     pah[kc], b0l);
                    mma16816(y[dg * 2],     pal[kc], b0h);
                    mma16816(y[dg * 2 + 1], pah[kc], b1h);
                    mma16816(y[dg * 2 + 1], pah[kc], b1l);
                    mma16816(y[dg * 2 + 1], pal[kc], b1h);
                }
            }
        }
        __syncthreads();
    }

    // ---- epilogue: y /= l -> bf16 hi/lo into g_yh/g_yl [b,n,c] ----
    const int bb = bh >> 4, hh = bh & 15;
    const float inv0 = 1.f / l0, inv1 = 1.f / l1;
    const int r0g = q0 + wid * 16 + (lane >> 2);
    size_t row0 = ((size_t)bb * Nseq + r0g) * Cdim + hh * Dh + (lane & 3) * 2;
    size_t row1 = row0 + (size_t)8 * Cdim;
#pragma unroll
    for (int dt = 0; dt < 8; dt++) {
        float v0 = y[dt][0] * inv0, v1 = y[dt][1] * inv0;
        float v2 = y[dt][2] * inv1, v3 = y[dt][3] * inv1;
        __nv_bfloat16 h0 = __float2bfloat16_rn(v0);
        __nv_bfloat16 h1 = __float2bfloat16_rn(v1);
        __nv_bfloat16 h2 = __float2bfloat16_rn(v2);
        __nv_bfloat16 h3 = __float2bfloat16_rn(v3);
        __nv_bfloat162 p01; p01.x = h0; p01.y = h1;
        __nv_bfloat162 p23; p23.x = h2; p23.y = h3;
        uint32_t u01, u23; memcpy(&u01, &p01, 4); memcpy(&u23, &p23, 4);
        *(uint32_t*)&g_yh[row0 + dt * 8] = u01;
        *(uint32_t*)&g_yh[row1 + dt * 8] = u23;
        *(uint32_t*)&g_yl[row0 + dt * 8] = pack2(v0 - __bfloat162float(h0),
                                                 v1 - __bfloat162float(h1));
        *(uint32_t*)&g_yl[row1 + dt * 8] = pack2(v2 - __bfloat162float(h2),
                                                 v3 - __bfloat162float(h3));
    }
}

// ---------------------------------------------------------------------------
extern "C" void kernel_launch(void* const* d_in, const int* in_sizes, int n_in,
                              void* d_out, int out_size)
{
    const float* x      = (const float*)d_in[0];   // [4,2048,1024]
    const float* w_attn = (const float*)d_in[1];   // [1024,3072]
    const float* w_proj = (const float*)d_in[2];   // [1024,1024]
    float* out = (float*)d_out;                    // [4,2048,1024]
    (void)in_sizes; (void)n_in; (void)out_size;

    // Dynamic-smem opt-in (idempotent; not a stream op, capture-safe).
    static bool attr_done = false;
    if (!attr_done) {
        cudaFuncSetAttribute(mma_gemm<0>, cudaFuncAttributeMaxDynamicSharedMemorySize, GSMEM);
        cudaFuncSetAttribute(mma_gemm<1>, cudaFuncAttributeMaxDynamicSharedMemorySize, GSMEM);
        attr_done = true;
    }

    // 0) Pre-passes: weight transpose+split, activation split
    split_transpose<0><<<dim3(3 * Cdim / 32, Cdim / 32), dim3(32, 8)>>>(w_attn, 3 * Cdim);
    split_transpose<1><<<dim3(Cdim / 32, Cdim / 32), dim3(32, 8)>>>(w_proj, Cdim);
    split_act<<<(Bz * Nseq * Cdim) / 1024, 256>>>(x);

    // 1) QKV projection -> bf16 hi/lo per-head layouts (q pre-scaled)
    mma_gemm<0><<<dim3(3 * Cdim / 128, (Bz * Nseq) / 128), 256, GSMEM>>>(nullptr);

    // 2) Flash attention (mma.sync) -> g_yh/g_yl bf16
    attn_mma<<<dim3(Nseq / 64, BHn), 128>>>();

    // 3) Output projection -> d_out (fp32)
    mma_gemm<1><<<dim3(Cdim / 128, (Bz * Nseq) / 128), 256, GSMEM>>>(out);
}

// round 16
// speedup vs baseline: 1.0862x; 1.0862x over previous
#include <cuda_runtime.h>
#include <cuda_bf16.h>
#include <cstdint>
#include <cstring>

// Problem constants
#define Bz   4
#define Nseq 2048
#define Cdim 1024
#define Hn   16
#define Dh   64
#define BHn  (Bz * Hn)

// Scratch (device globals; referenced ONLY inside device code).
__device__ __nv_bfloat16 g_qh[(size_t)BHn * Nseq * Dh];
__device__ __nv_bfloat16 g_ql[(size_t)BHn * Nseq * Dh];
__device__ __nv_bfloat16 g_kh[(size_t)BHn * Nseq * Dh];
__device__ __nv_bfloat16 g_kl[(size_t)BHn * Nseq * Dh];
__device__ __nv_bfloat16 g_vh[(size_t)BHn * Nseq * Dh];
__device__ __nv_bfloat16 g_vl[(size_t)BHn * Nseq * Dh];
__device__ __nv_bfloat16 g_xh[(size_t)Bz * Nseq * Cdim];
__device__ __nv_bfloat16 g_xl[(size_t)Bz * Nseq * Cdim];
__device__ __nv_bfloat16 g_yh[(size_t)Bz * Nseq * Cdim];
__device__ __nv_bfloat16 g_yl[(size_t)Bz * Nseq * Cdim];
__device__ __nv_bfloat16 g_w1t_hi[(size_t)3 * Cdim * Cdim];
__device__ __nv_bfloat16 g_w1t_lo[(size_t)3 * Cdim * Cdim];
__device__ __nv_bfloat16 g_w2t_hi[(size_t)Cdim * Cdim];
__device__ __nv_bfloat16 g_w2t_lo[(size_t)Cdim * Cdim];

// ---------------------------------------------------------------------------
// Warp-MMA helpers (base PTX)
// ---------------------------------------------------------------------------
__device__ __forceinline__ uint32_t smem_u32(const void* p) {
    uint32_t a;
    asm("{ .reg .u64 t; cvta.to.shared.u64 t, %1; cvt.u32.u64 %0, t; }" : "=r"(a) : "l"(p));
    return a;
}
__device__ __forceinline__ void ldsm4(uint32_t* r, uint32_t addr) {
    asm volatile("ldmatrix.sync.aligned.m8n8.x4.shared.b16 {%0,%1,%2,%3}, [%4];"
                 : "=r"(r[0]), "=r"(r[1]), "=r"(r[2]), "=r"(r[3]) : "r"(addr));
}
__device__ __forceinline__ void ldsm4t(uint32_t* r, uint32_t addr) {
    asm volatile("ldmatrix.sync.aligned.m8n8.x4.trans.shared.b16 {%0,%1,%2,%3}, [%4];"
                 : "=r"(r[0]), "=r"(r[1]), "=r"(r[2]), "=r"(r[3]) : "r"(addr));
}
__device__ __forceinline__ void mma16816(float* c, const uint32_t* a, const uint32_t* b) {
    asm volatile(
        "mma.sync.aligned.m16n8k16.row.col.f32.bf16.bf16.f32 "
        "{%0,%1,%2,%3}, {%4,%5,%6,%7}, {%8,%9}, {%0,%1,%2,%3};"
        : "+f"(c[0]), "+f"(c[1]), "+f"(c[2]), "+f"(c[3])
        : "r"(a[0]), "r"(a[1]), "r"(a[2]), "r"(a[3]), "r"(b[0]), "r"(b[1]));
}
__device__ __forceinline__ void cpa16(uint32_t daddr, const void* g) {
    asm volatile("cp.async.cg.shared.global [%0], [%1], 16;" :: "r"(daddr), "l"(g));
}
__device__ __forceinline__ void cpa_commit() { asm volatile("cp.async.commit_group;"); }
template <int N> __device__ __forceinline__ void cpa_wait() {
    asm volatile("cp.async.wait_group %0;" :: "n"(N));
}
__device__ __forceinline__ uint32_t pack2(float a, float b) {
    __nv_bfloat162 t;
    t.x = __float2bfloat16_rn(a); t.y = __float2bfloat16_rn(b);
    uint32_t u; memcpy(&u, &t, 4); return u;
}

// ---------------------------------------------------------------------------
// Weight pre-pass: w [K=1024, F] fp32 -> hi/lo [F, 1024] bf16 (split transpose)
// ---------------------------------------------------------------------------
template <int W>
__global__ __launch_bounds__(256)
void split_transpose(const float* __restrict__ w, int F)
{
    __nv_bfloat16* hi = (W == 0) ? g_w1t_hi : g_w2t_hi;
    __nv_bfloat16* lo = (W == 0) ? g_w1t_lo : g_w2t_lo;
    __shared__ float t[32][33];
    const int f0 = blockIdx.x * 32, k0 = blockIdx.y * 32;
    const int x = threadIdx.x, y0 = threadIdx.y;
#pragma unroll
    for (int r = 0; r < 4; r++) {
        int ky = y0 + r * 8;
        t[ky][x] = w[(size_t)(k0 + ky) * F + f0 + x];
    }
    __syncthreads();
#pragma unroll
    for (int r = 0; r < 4; r++) {
        int fy = y0 + r * 8;
        float v = t[x][fy];
        __nv_bfloat16 h = __float2bfloat16_rn(v);
        __nv_bfloat16 l = __float2bfloat16_rn(v - __bfloat162float(h));
        size_t o = (size_t)(f0 + fy) * 1024 + k0 + x;
        hi[o] = h; lo[o] = l;
    }
}

// ---------------------------------------------------------------------------
// Activation pre-pass: x fp32 -> g_xh/g_xl bf16
// ---------------------------------------------------------------------------
__global__ __launch_bounds__(256)
void split_act(const float* __restrict__ x)
{
    size_t i4 = ((size_t)blockIdx.x * 256 + threadIdx.x) * 4;
    float4 v = *(const float4*)(x + i4);
    __nv_bfloat16 hx = __float2bfloat16_rn(v.x);
    __nv_bfloat16 hy = __float2bfloat16_rn(v.y);
    __nv_bfloat16 hz = __float2bfloat16_rn(v.z);
    __nv_bfloat16 hw = __float2bfloat16_rn(v.w);
    uint2 hh, ll;
    __nv_bfloat162 h01; h01.x = hx; h01.y = hy;
    __nv_bfloat162 h23; h23.x = hz; h23.y = hw;
    memcpy(&hh.x, &h01, 4); memcpy(&hh.y, &h23, 4);
    ll.x = pack2(v.x - __bfloat162float(hx), v.y - __bfloat162float(hy));
    ll.y = pack2(v.z - __bfloat162float(hz), v.w - __bfloat162float(hw));
    *(uint2*)(g_xh + i4) = hh;
    *(uint2*)(g_xl + i4) = ll;
}

// ---------------------------------------------------------------------------
// mma.sync GEMM, all-bf16 inputs (pre-split), BK=32, TWO-stage cp.async
// pipeline (R14's proven one-barrier scheme — R15's 3rd stage regressed),
// dynamic smem 80KB. Chunk processed in two k=16 halves to keep the frag
// register set identical to R14 (regs ~128 -> 2 CTAs/SM).
// Invariant at top of iter kt: exactly one pending cp.async group (stage b).
// cpa_wait<0> drains it; barrier publishes b and proves ldsm of b^1 done;
// issue(kt+1) into b^1 then overlaps both ldsm+MMA half-bursts.
// MODE 0: A = g_xh/l, B = g_w1t -> scatter q/k/v bf16 hi/lo (q scaled 0.125)
// MODE 1: A = g_yh/l, B = g_w2t -> row-major fp32 Cout
// ---------------------------------------------------------------------------
#define BK2    32
#define ASTR2  40                       // b16 row stride (80B): conflict-free (R6-proven)
#define ARR_B  (128 * ASTR2 * 2)        // 10240 B per array
#define OFF2_AH 0
#define OFF2_AL (1 * ARR_B)
#define OFF2_BH (2 * ARR_B)
#define OFF2_BL (3 * ARR_B)
#define BUF2   (4 * ARR_B)              // 40960 B per stage
#define GSMEM  (2 * BUF2)               // 81920 B (dynamic, opt-in)
#define NKC2   (1024 / BK2)             // 32 chunks

template <int MODE>
__global__ __launch_bounds__(256, 2)
void mma_gemm(float* __restrict__ Cout)
{
    extern __shared__ __align__(128) char smem[];
    const uint32_t sbase = smem_u32(smem);
    const int tid  = threadIdx.x;
    const int wid  = tid >> 5, lane = tid & 31;
    const int wm   = wid >> 2;
    const int wn   = wid & 3;
    const int bM   = blockIdx.y * 128, bN = blockIdx.x * 128;

    const __nv_bfloat16* Ah = ((MODE == 0) ? g_xh : g_yh) + (size_t)bM * 1024;
    const __nv_bfloat16* Al = ((MODE == 0) ? g_xl : g_yl) + (size_t)bM * 1024;
    const __nv_bfloat16* Bh = ((MODE == 0) ? g_w1t_hi : g_w2t_hi) + (size_t)bN * 1024;
    const __nv_bfloat16* Bl = ((MODE == 0) ? g_w1t_lo : g_w2t_lo) + (size_t)bN * 1024;

    float acc[4][4][4];
#pragma unroll
    for (int i = 0; i < 4; i++)
#pragma unroll
        for (int j = 0; j < 4; j++)
#pragma unroll
            for (int r = 0; r < 4; r++) acc[i][j][r] = 0.f;

    // cp.async: per stage per array 128 rows x 64B = 512 x 16B; 256 thr -> 2 each.
    const int ldR = tid >> 2, ldQ = tid & 3;   // row 0..63(+64), quarter 0..3
    auto issue = [&](int kt, int b) {
        uint32_t dbase = sbase + b * BUF2;
        const int k0 = kt * BK2;
#pragma unroll
        for (int i = 0; i < 2; i++) {
            int r = ldR + i * 64;
            uint32_t doff = (uint32_t)(r * ASTR2 + ldQ * 8) * 2;
            size_t goff = (size_t)r * 1024 + k0 + ldQ * 8;
            cpa16(dbase + OFF2_AH + doff, Ah + goff);
            cpa16(dbase + OFF2_AL + doff, Al + goff);
            cpa16(dbase + OFF2_BH + doff, Bh + goff);
            cpa16(dbase + OFF2_BL + doff, Bl + goff);
        }
        cpa_commit();
    };

    const uint32_t aRow = wm * 64 + (lane & 15);
    const uint32_t aCol = (uint32_t)(lane >> 4) << 3;
    const uint32_t bRow = wn * 32 + (((uint32_t)(lane >> 4)) << 3) + (lane & 7);
    const uint32_t bCol = (((uint32_t)(lane >> 3)) & 1) << 3;

    issue(0, 0);
    for (int kt = 0; kt < NKC2; kt++) {
        const int b = kt & 1;
        cpa_wait<0>();                 // drain the ONE pending group (stage b)
        __syncthreads();               // publish stage b; prior ldsm of b^1 done

        if (kt + 1 < NKC2) issue(kt + 1, b ^ 1);   // overlaps both half-bursts

        const uint32_t base = sbase + b * BUF2;
#pragma unroll
        for (int ks = 0; ks < BK2; ks += 16) {
            uint32_t ah[4][4], al[4][4], bh[4][2], bl[4][2];
#pragma unroll
            for (int mt = 0; mt < 4; mt++) {
                uint32_t off = ((aRow + mt * 16) * ASTR2 + ks + aCol) * 2;
                ldsm4(ah[mt], base + OFF2_AH + off);
                ldsm4(al[mt], base + OFF2_AL + off);
            }
#pragma unroll
            for (int g = 0; g < 2; g++) {
                uint32_t off = ((bRow + g * 16) * ASTR2 + ks + bCol) * 2;
                uint32_t t[4];
                ldsm4(t, base + OFF2_BH + off);
                bh[g * 2][0] = t[0]; bh[g * 2][1] = t[1];
                bh[g * 2 + 1][0] = t[2]; bh[g * 2 + 1][1] = t[3];
                ldsm4(t, base + OFF2_BL + off);
                bl[g * 2][0] = t[0]; bl[g * 2][1] = t[1];
                bl[g * 2 + 1][0] = t[2]; bl[g * 2 + 1][1] = t[3];
            }
#pragma unroll
            for (int mt = 0; mt < 4; mt++)
#pragma unroll
                for (int nt = 0; nt < 4; nt++) {
                    mma16816(acc[mt][nt], ah[mt], bh[nt]);
                    mma16816(acc[mt][nt], ah[mt], bl[nt]);
                    mma16816(acc[mt][nt], al[mt], bh[nt]);
                }
        }
    }

    const int rq = lane >> 2, cq = (lane & 3) * 2;
#pragma unroll
    for (int mt = 0; mt < 4; mt++) {
        int m0 = bM + wm * 64 + mt * 16 + rq;
#pragma unroll
        for (int nt = 0; nt < 4; nt++) {
            int f = bN + wn * 32 + nt * 8 + cq;
            if (MODE == 0) {
                int sec = f >> 10, cc = f & (Cdim - 1);
                int h = cc >> 6, d = cc & 63;
                __nv_bfloat16* dhp = (sec == 0) ? g_qh : (sec == 1) ? g_kh : g_vh;
                __nv_bfloat16* dlp = (sec == 0) ? g_ql : (sec == 1) ? g_kl : g_vl;
                float scale = (sec == 0) ? 0.125f : 1.0f;
#pragma unroll
                for (int half = 0; half < 2; half++) {
                    int m = m0 + half * 8;
                    float v0 = acc[mt][nt][half * 2] * scale;
                    float v1 = acc[mt][nt][half * 2 + 1] * scale;
                    __nv_bfloat16 h0 = __float2bfloat16_rn(v0);
                    __nv_bfloat16 h1 = __float2bfloat16_rn(v1);
                    size_t idx = (((size_t)(m >> 11) * Hn + h) * Nseq + (m & (Nseq - 1))) * Dh + d;
                    __nv_bfloat162 hp; hp.x = h0; hp.y = h1;
                    uint32_t hw; memcpy(&hw, &hp, 4);
                    *(uint32_t*)&dhp[idx] = hw;
                    *(uint32_t*)&dlp[idx] = pack2(v0 - __bfloat162float(h0),
                                                  v1 - __bfloat162float(h1));
                }
            } else {
#pragma unroll
                for (int half = 0; half < 2; half++) {
                    int m = m0 + half * 8;
                    float* p = Cout + (size_t)m * Cdim + f;
                    *(float2*)p = make_float2(acc[mt][nt][half * 2], acc[mt][nt][half * 2 + 1]);
                }
            }
        }
    }
}

// ---------------------------------------------------------------------------
// Flash attention via mma.sync (verified R8-R15, unchanged).
// Pipeline order here is the PROVEN one: issue(next) BEFORE cpa_wait<1>.
// ---------------------------------------------------------------------------
#define AKT   32
#define ANT   (Nseq / AKT)
#define DSTR  72
#define ATILE (AKT * DSTR * 2)
#define ABUF  (4 * ATILE)

__global__ __launch_bounds__(128, 4)
void attn_mma()
{
    __shared__ __align__(128) char smem[2 * ABUF];
    const uint32_t sbase = smem_u32(smem);
    const int tid = threadIdx.x, lane = tid & 31, wid = tid >> 5;
    const int bh = blockIdx.y, q0 = blockIdx.x * 64;

    const __nv_bfloat16* Qhp = g_qh + ((size_t)bh * Nseq + q0) * Dh;
    const __nv_bfloat16* Qlp = g_ql + ((size_t)bh * Nseq + q0) * Dh;
    const __nv_bfloat16* Khp = g_kh + (size_t)bh * Nseq * Dh;
    const __nv_bfloat16* Klp = g_kl + (size_t)bh * Nseq * Dh;
    const __nv_bfloat16* Vhp = g_vh + (size_t)bh * Nseq * Dh;
    const __nv_bfloat16* Vlp = g_vl + (size_t)bh * Nseq * Dh;

#pragma unroll
    for (int i = 0; i < 4; i++) {
        int e = tid + i * 128;
        int r = e >> 3, c8 = e & 7;
        *(uint4*)(smem + r * (DSTR * 2) + c8 * 16) =
            *(const uint4*)(Qhp + (size_t)r * Dh + c8 * 8);
        *(uint4*)(smem + ABUF + r * (DSTR * 2) + c8 * 16) =
            *(const uint4*)(Qlp + (size_t)r * Dh + c8 * 8);
    }
    __syncthreads();

    uint32_t qh[4][4], ql[4][4];
    {
        uint32_t row = wid * 16 + (lane & 15);
        uint32_t col = ((uint32_t)(lane >> 4) & 1) << 3;
#pragma unroll
        for (int kc = 0; kc < 4; kc++) {
            uint32_t off = (row * DSTR + kc * 16 + col) * 2;
            ldsm4(qh[kc], sbase + off);
            ldsm4(ql[kc], sbase + ABUF + off);
        }
    }
    __syncthreads();

    float m0 = -1e30f, m1 = -1e30f, l0 = 0.f, l1 = 0.f;
    float y[8][4];
#pragma unroll
    for (int i = 0; i < 8; i++)
#pragma unroll
        for (int j = 0; j < 4; j++) y[i][j] = 0.f;

    auto issue = [&](int t, int b) {
        uint32_t dbase = sbase + b * ABUF;
        const __nv_bfloat16* kh = Khp + (size_t)t * AKT * Dh;
        const __nv_bfloat16* kl = Klp + (size_t)t * AKT * Dh;
        const __nv_bfloat16* vh = Vhp + (size_t)t * AKT * Dh;
        const __nv_bfloat16* vl = Vlp + (size_t)t * AKT * Dh;
#pragma unroll
        for (int i = 0; i < 2; i++) {
            int e = tid + i * 128;
            int r = e >> 3, c8 = e & 7;
            uint32_t doff = r * (DSTR * 2) + c8 * 16;
            size_t goff = (size_t)r * Dh + c8 * 8;
            cpa16(dbase + 0 * ATILE + doff, kh + goff);
            cpa16(dbase + 1 * ATILE + doff, kl + goff);
            cpa16(dbase + 2 * ATILE + doff, vh + goff);
            cpa16(dbase + 3 * ATILE + doff, vl + goff);
        }
        cpa_commit();
    };

    issue(0, 0);
    for (int t = 0; t < ANT; t++) {
        const int b = t & 1;
        if (t + 1 < ANT) { issue(t + 1, b ^ 1); cpa_wait<1>(); }
        else             { cpa_wait<0>(); }
        __syncthreads();

        const uint32_t kb = sbase + b * ABUF;

        float s[4][4];
#pragma unroll
        for (int i = 0; i < 4; i++)
#pragma unroll
            for (int j = 0; j < 4; j++) s[i][j] = 0.f;
        {
            uint32_t brow = (((uint32_t)(lane >> 4)) << 3) + (lane & 7);
            uint32_t bcol = (((uint32_t)(lane >> 3)) & 1) << 3;
#pragma unroll
            for (int kc = 0; kc < 4; kc++) {
                uint32_t kfh[8], kfl[8];
#pragma unroll
                for (int kg = 0; kg < 2; kg++) {
                    uint32_t off = ((brow + kg * 16) * DSTR + kc * 16 + bcol) * 2;
                    ldsm4(kfh + kg * 4, kb + 0 * ATILE + off);
                    ldsm4(kfl + kg * 4, kb + 1 * ATILE + off);
                }
#pragma unroll
                for (int nt = 0; nt < 4; nt++) {
                    uint32_t bhf[2] = {kfh[nt * 2], kfh[nt * 2 + 1]};
                    uint32_t blf[2] = {kfl[nt * 2], kfl[nt * 2 + 1]};
                    mma16816(s[nt], qh[kc], bhf);
                    mma16816(s[nt], qh[kc], blf);
                    mma16816(s[nt], ql[kc], bhf);
                }
            }
        }

        float mx0 = s[0][0], mx1 = s[0][2];
#pragma unroll
        for (int nt = 0; nt < 4; nt++) {
            mx0 = fmaxf(mx0, fmaxf(s[nt][0], s[nt][1]));
            mx1 = fmaxf(mx1, fmaxf(s[nt][2], s[nt][3]));
        }
#pragma unroll
        for (int off = 1; off <= 2; off <<= 1) {
            mx0 = fmaxf(mx0, __shfl_xor_sync(0xffffffffu, mx0, off));
            mx1 = fmaxf(mx1, __shfl_xor_sync(0xffffffffu, mx1, off));
        }
        float mn0 = fmaxf(m0, mx0), mn1 = fmaxf(m1, mx1);
        float al0 = __expf(m0 - mn0), al1 = __expf(m1 - mn1);
        m0 = mn0; m1 = mn1;

        float ls0 = 0.f, ls1 = 0.f;
#pragma unroll
        for (int nt = 0; nt < 4; nt++) {
            s[nt][0] = __expf(s[nt][0] - mn0);
            s[nt][1] = __expf(s[nt][1] - mn0);
            s[nt][2] = __expf(s[nt][2] - mn1);
            s[nt][3] = __expf(s[nt][3] - mn1);
            ls0 += s[nt][0] + s[nt][1];
            ls1 += s[nt][2] + s[nt][3];
        }
#pragma unroll
        for (int off = 1; off <= 2; off <<= 1) {
            ls0 += __shfl_xor_sync(0xffffffffu, ls0, off);
            ls1 += __shfl_xor_sync(0xffffffffu, ls1, off);
        }
        l0 = l0 * al0 + ls0;
        l1 = l1 * al1 + ls1;
#pragma unroll
        for (int dt = 0; dt < 8; dt++) {
            y[dt][0] *= al0; y[dt][1] *= al0;
            y[dt][2] *= al1; y[dt][3] *= al1;
        }

        uint32_t pah[2][4], pal[2][4];
#pragma unroll
        for (int kc = 0; kc < 2; kc++) {
#pragma unroll
            for (int q = 0; q < 4; q++) {
                int nt = 2 * kc + (q >> 1);
                int j0 = (q & 1) * 2;
                float p0 = s[nt][j0], p1 = s[nt][j0 + 1];
                __nv_bfloat16 h0 = __float2bfloat16_rn(p0);
                __nv_bfloat16 h1 = __float2bfloat16_rn(p1);
                __nv_bfloat162 hp; hp.x = h0; hp.y = h1;
                memcpy(&pah[kc][q], &hp, 4);
                pal[kc][q] = pack2(p0 - __bfloat162float(h0), p1 - __bfloat162float(h1));
            }
        }

        {
            uint32_t vrow = lane & 15;
            uint32_t vcol = ((uint32_t)(lane >> 4) & 1) << 3;
#pragma unroll
            for (int kc = 0; kc < 2; kc++) {
#pragma unroll
                for (int dg = 0; dg < 4; dg++) {
                    uint32_t off = ((kc * 16 + vrow) * DSTR + dg * 16 + vcol) * 2;
                    uint32_t vfh[4], vfl[4];
                    ldsm4t(vfh, kb + 2 * ATILE + off);
                    ldsm4t(vfl, kb + 3 * ATILE + off);
                    uint32_t b0h[2] = {vfh[0], vfh[1]}, b1h[2] = {vfh[2], vfh[3]};
                    uint32_t b0l[2] = {vfl[0], vfl[1]}, b1l[2] = {vfl[2], vfl[3]};
                    mma16816(y[dg * 2],     pah[kc], b0h);
                    mma16816(y[dg * 2],     pah[kc], b0l);
                    mma16816(y[dg * 2],     pal[kc], b0h);
                    mma16816(y[dg * 2 + 1], pah[kc], b1h);
                    mma16816(y[dg * 2 + 1], pah[kc], b1l);
                    mma16816(y[dg * 2 + 1], pal[kc], b1h);
                }
            }
        }
        __syncthreads();
    }

    // ---- epilogue: y /= l -> bf16 hi/lo into g_yh/g_yl [b,n,c] ----
    const int bb = bh >> 4, hh = bh & 15;
    const float inv0 = 1.f / l0, inv1 = 1.f / l1;
    const int r0g = q0 + wid * 16 + (lane >> 2);
    size_t row0 = ((size_t)bb * Nseq + r0g) * Cdim + hh * Dh + (lane & 3) * 2;
    size_t row1 = row0 + (size_t)8 * Cdim;
#pragma unroll
    for (int dt = 0; dt < 8; dt++) {
        float v0 = y[dt][0] * inv0, v1 = y[dt][1] * inv0;
        float v2 = y[dt][2] * inv1, v3 = y[dt][3] * inv1;
        __nv_bfloat16 h0 = __float2bfloat16_rn(v0);
        __nv_bfloat16 h1 = __float2bfloat16_rn(v1);
        __nv_bfloat16 h2 = __float2bfloat16_rn(v2);
        __nv_bfloat16 h3 = __float2bfloat16_rn(v3);
        __nv_bfloat162 p01; p01.x = h0; p01.y = h1;
        __nv_bfloat162 p23; p23.x = h2; p23.y = h3;
        uint32_t u01, u23; memcpy(&u01, &p01, 4); memcpy(&u23, &p23, 4);
        *(uint32_t*)&g_yh[row0 + dt * 8] = u01;
        *(uint32_t*)&g_yh[row1 + dt * 8] = u23;
        *(uint32_t*)&g_yl[row0 + dt * 8] = pack2(v0 - __bfloat162float(h0),
                                                 v1 - __bfloat162float(h1));
        *(uint32_t*)&g_yl[row1 + dt * 8] = pack2(v2 - __bfloat162float(h2),
                                                 v3 - __bfloat162float(h3));
    }
}

// ---------------------------------------------------------------------------
extern "C" void kernel_launch(void* const* d_in, const int* in_sizes, int n_in,
                              void* d_out, int out_size)
{
    const float* x      = (const float*)d_in[0];   // [4,2048,1024]
    const float* w_attn = (const float*)d_in[1];   // [1024,3072]
    const float* w_proj = (const float*)d_in[2];   // [1024,1024]
    float* out = (float*)d_out;                    // [4,2048,1024]
    (void)in_sizes; (void)n_in; (void)out_size;

    // Dynamic-smem opt-in (idempotent host-side attribute; capture-safe).
    static bool attr_done = false;
    if (!attr_done) {
        cudaFuncSetAttribute(mma_gemm<0>, cudaFuncAttributeMaxDynamicSharedMemorySize, GSMEM);
        cudaFuncSetAttribute(mma_gemm<1>, cudaFuncAttributeMaxDynamicSharedMemorySize, GSMEM);
        attr_done = true;
    }

    // 0) Pre-passes: weight transpose+split, activation split
    split_transpose<0><<<dim3(3 * Cdim / 32, Cdim / 32), dim3(32, 8)>>>(w_attn, 3 * Cdim);
    split_transpose<1><<<dim3(Cdim / 32, Cdim / 32), dim3(32, 8)>>>(w_proj, Cdim);
    split_act<<<(Bz * Nseq * Cdim) / 1024, 256>>>(x);

    // 1) QKV projection -> bf16 hi/lo per-head layouts (q pre-scaled)
    mma_gemm<0><<<dim3(3 * Cdim / 128, (Bz * Nseq) / 128), 256, GSMEM>>>(nullptr);

    // 2) Flash attention (mma.sync) -> g_yh/g_yl bf16
    attn_mma<<<dim3(Nseq / 64, BHn), 128>>>();

    // 3) Output projection -> d_out (fp32)
    mma_gemm<1><<<dim3(Cdim / 128, (Bz * Nseq) / 128), 256, GSMEM>>>(out);
}

// round 17
// speedup vs baseline: 1.0900x; 1.0035x over previous
#include <cuda_runtime.h>
#include <cuda_bf16.h>
#include <cstdint>
#include <cstring>

// Problem constants
#define Bz   4
#define Nseq 2048
#define Cdim 1024
#define Hn   16
#define Dh   64
#define BHn  (Bz * Hn)

// Scratch (device globals; referenced ONLY inside device code).
__device__ __nv_bfloat16 g_qh[(size_t)BHn * Nseq * Dh];
__device__ __nv_bfloat16 g_ql[(size_t)BHn * Nseq * Dh];
__device__ __nv_bfloat16 g_kh[(size_t)BHn * Nseq * Dh];
__device__ __nv_bfloat16 g_kl[(size_t)BHn * Nseq * Dh];
__device__ __nv_bfloat16 g_vh[(size_t)BHn * Nseq * Dh];
__device__ __nv_bfloat16 g_vl[(size_t)BHn * Nseq * Dh];
__device__ __nv_bfloat16 g_xh[(size_t)Bz * Nseq * Cdim];
__device__ __nv_bfloat16 g_xl[(size_t)Bz * Nseq * Cdim];
__device__ __nv_bfloat16 g_yh[(size_t)Bz * Nseq * Cdim];
__device__ __nv_bfloat16 g_yl[(size_t)Bz * Nseq * Cdim];
__device__ __nv_bfloat16 g_w1t_hi[(size_t)3 * Cdim * Cdim];
__device__ __nv_bfloat16 g_w1t_lo[(size_t)3 * Cdim * Cdim];
__device__ __nv_bfloat16 g_w2t_hi[(size_t)Cdim * Cdim];
__device__ __nv_bfloat16 g_w2t_lo[(size_t)Cdim * Cdim];

// ---------------------------------------------------------------------------
// Warp-MMA helpers (base PTX)
// ---------------------------------------------------------------------------
__device__ __forceinline__ uint32_t smem_u32(const void* p) {
    uint32_t a;
    asm("{ .reg .u64 t; cvta.to.shared.u64 t, %1; cvt.u32.u64 %0, t; }" : "=r"(a) : "l"(p));
    return a;
}
__device__ __forceinline__ void ldsm4(uint32_t* r, uint32_t addr) {
    asm volatile("ldmatrix.sync.aligned.m8n8.x4.shared.b16 {%0,%1,%2,%3}, [%4];"
                 : "=r"(r[0]), "=r"(r[1]), "=r"(r[2]), "=r"(r[3]) : "r"(addr));
}
__device__ __forceinline__ void ldsm4t(uint32_t* r, uint32_t addr) {
    asm volatile("ldmatrix.sync.aligned.m8n8.x4.trans.shared.b16 {%0,%1,%2,%3}, [%4];"
                 : "=r"(r[0]), "=r"(r[1]), "=r"(r[2]), "=r"(r[3]) : "r"(addr));
}
__device__ __forceinline__ void mma16816(float* c, const uint32_t* a, const uint32_t* b) {
    asm volatile(
        "mma.sync.aligned.m16n8k16.row.col.f32.bf16.bf16.f32 "
        "{%0,%1,%2,%3}, {%4,%5,%6,%7}, {%8,%9}, {%0,%1,%2,%3};"
        : "+f"(c[0]), "+f"(c[1]), "+f"(c[2]), "+f"(c[3])
        : "r"(a[0]), "r"(a[1]), "r"(a[2]), "r"(a[3]), "r"(b[0]), "r"(b[1]));
}
__device__ __forceinline__ void cpa16(uint32_t daddr, const void* g) {
    asm volatile("cp.async.cg.shared.global [%0], [%1], 16;" :: "r"(daddr), "l"(g));
}
__device__ __forceinline__ void cpa_commit() { asm volatile("cp.async.commit_group;"); }
template <int N> __device__ __forceinline__ void cpa_wait() {
    asm volatile("cp.async.wait_group %0;" :: "n"(N));
}
__device__ __forceinline__ uint32_t pack2(float a, float b) {
    __nv_bfloat162 t;
    t.x = __float2bfloat16_rn(a); t.y = __float2bfloat16_rn(b);
    uint32_t u; memcpy(&u, &t, 4); return u;
}

// ---------------------------------------------------------------------------
// Weight pre-pass: w [K=1024, F] fp32 -> hi/lo [F, 1024] bf16 (split transpose)
// ---------------------------------------------------------------------------
template <int W>
__global__ __launch_bounds__(256)
void split_transpose(const float* __restrict__ w, int F)
{
    __nv_bfloat16* hi = (W == 0) ? g_w1t_hi : g_w2t_hi;
    __nv_bfloat16* lo = (W == 0) ? g_w1t_lo : g_w2t_lo;
    __shared__ float t[32][33];
    const int f0 = blockIdx.x * 32, k0 = blockIdx.y * 32;
    const int x = threadIdx.x, y0 = threadIdx.y;
#pragma unroll
    for (int r = 0; r < 4; r++) {
        int ky = y0 + r * 8;
        t[ky][x] = w[(size_t)(k0 + ky) * F + f0 + x];
    }
    __syncthreads();
#pragma unroll
    for (int r = 0; r < 4; r++) {
        int fy = y0 + r * 8;
        float v = t[x][fy];
        __nv_bfloat16 h = __float2bfloat16_rn(v);
        __nv_bfloat16 l = __float2bfloat16_rn(v - __bfloat162float(h));
        size_t o = (size_t)(f0 + fy) * 1024 + k0 + x;
        hi[o] = h; lo[o] = l;
    }
}

// ---------------------------------------------------------------------------
// Activation pre-pass: x fp32 -> g_xh/g_xl bf16
// ---------------------------------------------------------------------------
__global__ __launch_bounds__(256)
void split_act(const float* __restrict__ x)
{
    size_t i4 = ((size_t)blockIdx.x * 256 + threadIdx.x) * 4;
    float4 v = *(const float4*)(x + i4);
    __nv_bfloat16 hx = __float2bfloat16_rn(v.x);
    __nv_bfloat16 hy = __float2bfloat16_rn(v.y);
    __nv_bfloat16 hz = __float2bfloat16_rn(v.z);
    __nv_bfloat16 hw = __float2bfloat16_rn(v.w);
    uint2 hh, ll;
    __nv_bfloat162 h01; h01.x = hx; h01.y = hy;
    __nv_bfloat162 h23; h23.x = hz; h23.y = hw;
    memcpy(&hh.x, &h01, 4); memcpy(&hh.y, &h23, 4);
    ll.x = pack2(v.x - __bfloat162float(hx), v.y - __bfloat162float(hy));
    ll.y = pack2(v.z - __bfloat162float(hz), v.w - __bfloat162float(hw));
    *(uint2*)(g_xh + i4) = hh;
    *(uint2*)(g_xl + i4) = ll;
}

// ---------------------------------------------------------------------------
// mma.sync GEMM (R16-proven: BK=32, two-stage, one barrier/chunk, dyn smem)
// MODE 0: A = g_xh/l, B = g_w1t -> scatter q/k/v bf16 hi/lo (q scaled 0.125)
// MODE 1: A = g_yh/l, B = g_w2t -> row-major fp32 Cout
// ---------------------------------------------------------------------------
#define BK2    32
#define ASTR2  40
#define ARR_B  (128 * ASTR2 * 2)
#define OFF2_AH 0
#define OFF2_AL (1 * ARR_B)
#define OFF2_BH (2 * ARR_B)
#define OFF2_BL (3 * ARR_B)
#define BUF2   (4 * ARR_B)
#define GSMEM  (2 * BUF2)
#define NKC2   (1024 / BK2)

template <int MODE>
__global__ __launch_bounds__(256, 2)
void mma_gemm(float* __restrict__ Cout)
{
    extern __shared__ __align__(128) char smem[];
    const uint32_t sbase = smem_u32(smem);
    const int tid  = threadIdx.x;
    const int wid  = tid >> 5, lane = tid & 31;
    const int wm   = wid >> 2;
    const int wn   = wid & 3;
    const int bM   = blockIdx.y * 128, bN = blockIdx.x * 128;

    const __nv_bfloat16* Ah = ((MODE == 0) ? g_xh : g_yh) + (size_t)bM * 1024;
    const __nv_bfloat16* Al = ((MODE == 0) ? g_xl : g_yl) + (size_t)bM * 1024;
    const __nv_bfloat16* Bh = ((MODE == 0) ? g_w1t_hi : g_w2t_hi) + (size_t)bN * 1024;
    const __nv_bfloat16* Bl = ((MODE == 0) ? g_w1t_lo : g_w2t_lo) + (size_t)bN * 1024;

    float acc[4][4][4];
#pragma unroll
    for (int i = 0; i < 4; i++)
#pragma unroll
        for (int j = 0; j < 4; j++)
#pragma unroll
            for (int r = 0; r < 4; r++) acc[i][j][r] = 0.f;

    const int ldR = tid >> 2, ldQ = tid & 3;
    auto issue = [&](int kt, int b) {
        uint32_t dbase = sbase + b * BUF2;
        const int k0 = kt * BK2;
#pragma unroll
        for (int i = 0; i < 2; i++) {
            int r = ldR + i * 64;
            uint32_t doff = (uint32_t)(r * ASTR2 + ldQ * 8) * 2;
            size_t goff = (size_t)r * 1024 + k0 + ldQ * 8;
            cpa16(dbase + OFF2_AH + doff, Ah + goff);
            cpa16(dbase + OFF2_AL + doff, Al + goff);
            cpa16(dbase + OFF2_BH + doff, Bh + goff);
            cpa16(dbase + OFF2_BL + doff, Bl + goff);
        }
        cpa_commit();
    };

    const uint32_t aRow = wm * 64 + (lane & 15);
    const uint32_t aCol = (uint32_t)(lane >> 4) << 3;
    const uint32_t bRow = wn * 32 + (((uint32_t)(lane >> 4)) << 3) + (lane & 7);
    const uint32_t bCol = (((uint32_t)(lane >> 3)) & 1) << 3;

    issue(0, 0);
    for (int kt = 0; kt < NKC2; kt++) {
        const int b = kt & 1;
        cpa_wait<0>();
        __syncthreads();

        if (kt + 1 < NKC2) issue(kt + 1, b ^ 1);

        const uint32_t base = sbase + b * BUF2;
#pragma unroll
        for (int ks = 0; ks < BK2; ks += 16) {
            uint32_t ah[4][4], al[4][4], bh[4][2], bl[4][2];
#pragma unroll
            for (int mt = 0; mt < 4; mt++) {
                uint32_t off = ((aRow + mt * 16) * ASTR2 + ks + aCol) * 2;
                ldsm4(ah[mt], base + OFF2_AH + off);
                ldsm4(al[mt], base + OFF2_AL + off);
            }
#pragma unroll
            for (int g = 0; g < 2; g++) {
                uint32_t off = ((bRow + g * 16) * ASTR2 + ks + bCol) * 2;
                uint32_t t[4];
                ldsm4(t, base + OFF2_BH + off);
                bh[g * 2][0] = t[0]; bh[g * 2][1] = t[1];
                bh[g * 2 + 1][0] = t[2]; bh[g * 2 + 1][1] = t[3];
                ldsm4(t, base + OFF2_BL + off);
                bl[g * 2][0] = t[0]; bl[g * 2][1] = t[1];
                bl[g * 2 + 1][0] = t[2]; bl[g * 2 + 1][1] = t[3];
            }
#pragma unroll
            for (int mt = 0; mt < 4; mt++)
#pragma unroll
                for (int nt = 0; nt < 4; nt++) {
                    mma16816(acc[mt][nt], ah[mt], bh[nt]);
                    mma16816(acc[mt][nt], ah[mt], bl[nt]);
                    mma16816(acc[mt][nt], al[mt], bh[nt]);
                }
        }
    }

    const int rq = lane >> 2, cq = (lane & 3) * 2;
#pragma unroll
    for (int mt = 0; mt < 4; mt++) {
        int m0 = bM + wm * 64 + mt * 16 + rq;
#pragma unroll
        for (int nt = 0; nt < 4; nt++) {
            int f = bN + wn * 32 + nt * 8 + cq;
            if (MODE == 0) {
                int sec = f >> 10, cc = f & (Cdim - 1);
                int h = cc >> 6, d = cc & 63;
                __nv_bfloat16* dhp = (sec == 0) ? g_qh : (sec == 1) ? g_kh : g_vh;
                __nv_bfloat16* dlp = (sec == 0) ? g_ql : (sec == 1) ? g_kl : g_vl;
                float scale = (sec == 0) ? 0.125f : 1.0f;
#pragma unroll
                for (int half = 0; half < 2; half++) {
                    int m = m0 + half * 8;
                    float v0 = acc[mt][nt][half * 2] * scale;
                    float v1 = acc[mt][nt][half * 2 + 1] * scale;
                    __nv_bfloat16 h0 = __float2bfloat16_rn(v0);
                    __nv_bfloat16 h1 = __float2bfloat16_rn(v1);
                    size_t idx = (((size_t)(m >> 11) * Hn + h) * Nseq + (m & (Nseq - 1))) * Dh + d;
                    __nv_bfloat162 hp; hp.x = h0; hp.y = h1;
                    uint32_t hw; memcpy(&hw, &hp, 4);
                    *(uint32_t*)&dhp[idx] = hw;
                    *(uint32_t*)&dlp[idx] = pack2(v0 - __bfloat162float(h0),
                                                  v1 - __bfloat162float(h1));
                }
            } else {
#pragma unroll
                for (int half = 0; half < 2; half++) {
                    int m = m0 + half * 8;
                    float* p = Cout + (size_t)m * Cdim + f;
                    *(float2*)p = make_float2(acc[mt][nt][half * 2], acc[mt][nt][half * 2 + 1]);
                }
            }
        }
    }
}

// ---------------------------------------------------------------------------
// Flash attention via mma.sync — 128-query tiles, 256 threads (8 warps x 16
// rows; per-warp code identical to the R8-R16 proven path). Halves block
// count and K/V L2 traffic. Pipeline order: issue(next) BEFORE cpa_wait<1>.
// ---------------------------------------------------------------------------
#define AKT   32
#define ANT   (Nseq / AKT)
#define DSTR  72
#define ATILE (AKT * DSTR * 2)
#define ABUF  (4 * ATILE)               // 18432 B per stage

__global__ __launch_bounds__(256, 2)
void attn_mma()
{
    __shared__ __align__(128) char smem[2 * ABUF];   // 36864 B static
    const uint32_t sbase = smem_u32(smem);
    const int tid = threadIdx.x, lane = tid & 31, wid = tid >> 5;
    const int bh = blockIdx.y, q0 = blockIdx.x * 128;

    const __nv_bfloat16* Qhp = g_qh + ((size_t)bh * Nseq + q0) * Dh;
    const __nv_bfloat16* Qlp = g_ql + ((size_t)bh * Nseq + q0) * Dh;
    const __nv_bfloat16* Khp = g_kh + (size_t)bh * Nseq * Dh;
    const __nv_bfloat16* Klp = g_kl + (size_t)bh * Nseq * Dh;
    const __nv_bfloat16* Vhp = g_vh + (size_t)bh * Nseq * Dh;
    const __nv_bfloat16* Vlp = g_vl + (size_t)bh * Nseq * Dh;

    // ---- stage Q (128x64 hi/lo) into the two K/V buffers (exact fit) ----
#pragma unroll
    for (int i = 0; i < 4; i++) {
        int e = tid + i * 256;             // 1024 x 16B per array
        int r = e >> 3, c8 = e & 7;
        *(uint4*)(smem + r * (DSTR * 2) + c8 * 16) =
            *(const uint4*)(Qhp + (size_t)r * Dh + c8 * 8);
        *(uint4*)(smem + ABUF + r * (DSTR * 2) + c8 * 16) =
            *(const uint4*)(Qlp + (size_t)r * Dh + c8 * 8);
    }
    __syncthreads();

    uint32_t qh[4][4], ql[4][4];
    {
        uint32_t row = wid * 16 + (lane & 15);   // 0..127
        uint32_t col = ((uint32_t)(lane >> 4) & 1) << 3;
#pragma unroll
        for (int kc = 0; kc < 4; kc++) {
            uint32_t off = (row * DSTR + kc * 16 + col) * 2;
            ldsm4(qh[kc], sbase + off);
            ldsm4(ql[kc], sbase + ABUF + off);
        }
    }
    __syncthreads();   // staged Q consumed; buffers free for K/V

    float m0 = -1e30f, m1 = -1e30f, l0 = 0.f, l1 = 0.f;
    float y[8][4];
#pragma unroll
    for (int i = 0; i < 8; i++)
#pragma unroll
        for (int j = 0; j < 4; j++) y[i][j] = 0.f;

    // K/V issue: per array 32 rows x 8 chunks = 256 x 16B; one per thread.
    const int kvR = tid >> 3, kvC = tid & 7;
    auto issue = [&](int t, int b) {
        uint32_t dbase = sbase + b * ABUF;
        size_t goff = (size_t)(t * AKT + kvR) * Dh + kvC * 8;
        uint32_t doff = kvR * (DSTR * 2) + kvC * 16;
        cpa16(dbase + 0 * ATILE + doff, Khp + goff);
        cpa16(dbase + 1 * ATILE + doff, Klp + goff);
        cpa16(dbase + 2 * ATILE + doff, Vhp + goff);
        cpa16(dbase + 3 * ATILE + doff, Vlp + goff);
        cpa_commit();
    };

    issue(0, 0);
    for (int t = 0; t < ANT; t++) {
        const int b = t & 1;
        if (t + 1 < ANT) { issue(t + 1, b ^ 1); cpa_wait<1>(); }
        else             { cpa_wait<0>(); }
        __syncthreads();

        const uint32_t kb = sbase + b * ABUF;

        float s[4][4];
#pragma unroll
        for (int i = 0; i < 4; i++)
#pragma unroll
            for (int j = 0; j < 4; j++) s[i][j] = 0.f;
        {
            uint32_t brow = (((uint32_t)(lane >> 4)) << 3) + (lane & 7);
            uint32_t bcol = (((uint32_t)(lane >> 3)) & 1) << 3;
#pragma unroll
            for (int kc = 0; kc < 4; kc++) {
                uint32_t kfh[8], kfl[8];
#pragma unroll
                for (int kg = 0; kg < 2; kg++) {
                    uint32_t off = ((brow + kg * 16) * DSTR + kc * 16 + bcol) * 2;
                    ldsm4(kfh + kg * 4, kb + 0 * ATILE + off);
                    ldsm4(kfl + kg * 4, kb + 1 * ATILE + off);
                }
#pragma unroll
                for (int nt = 0; nt < 4; nt++) {
                    uint32_t bhf[2] = {kfh[nt * 2], kfh[nt * 2 + 1]};
                    uint32_t blf[2] = {kfl[nt * 2], kfl[nt * 2 + 1]};
                    mma16816(s[nt], qh[kc], bhf);
                    mma16816(s[nt], qh[kc], blf);
                    mma16816(s[nt], ql[kc], bhf);
                }
            }
        }

        float mx0 = s[0][0], mx1 = s[0][2];
#pragma unroll
        for (int nt = 0; nt < 4; nt++) {
            mx0 = fmaxf(mx0, fmaxf(s[nt][0], s[nt][1]));
            mx1 = fmaxf(mx1, fmaxf(s[nt][2], s[nt][3]));
        }
#pragma unroll
        for (int off = 1; off <= 2; off <<= 1) {
            mx0 = fmaxf(mx0, __shfl_xor_sync(0xffffffffu, mx0, off));
            mx1 = fmaxf(mx1, __shfl_xor_sync(0xffffffffu, mx1, off));
        }
        float mn0 = fmaxf(m0, mx0), mn1 = fmaxf(m1, mx1);
        float al0 = __expf(m0 - mn0), al1 = __expf(m1 - mn1);
        m0 = mn0; m1 = mn1;

        float ls0 = 0.f, ls1 = 0.f;
#pragma unroll
        for (int nt = 0; nt < 4; nt++) {
            s[nt][0] = __expf(s[nt][0] - mn0);
            s[nt][1] = __expf(s[nt][1] - mn0);
            s[nt][2] = __expf(s[nt][2] - mn1);
            s[nt][3] = __expf(s[nt][3] - mn1);
            ls0 += s[nt][0] + s[nt][1];
            ls1 += s[nt][2] + s[nt][3];
        }
#pragma unroll
        for (int off = 1; off <= 2; off <<= 1) {
            ls0 += __shfl_xor_sync(0xffffffffu, ls0, off);
            ls1 += __shfl_xor_sync(0xffffffffu, ls1, off);
        }
        l0 = l0 * al0 + ls0;
        l1 = l1 * al1 + ls1;
#pragma unroll
        for (int dt = 0; dt < 8; dt++) {
            y[dt][0] *= al0; y[dt][1] *= al0;
            y[dt][2] *= al1; y[dt][3] *= al1;
        }

        uint32_t pah[2][4], pal[2][4];
#pragma unroll
        for (int kc = 0; kc < 2; kc++) {
#pragma unroll
            for (int q = 0; q < 4; q++) {
                int nt = 2 * kc + (q >> 1);
                int j0 = (q & 1) * 2;
                float p0 = s[nt][j0], p1 = s[nt][j0 + 1];
                __nv_bfloat16 h0 = __float2bfloat16_rn(p0);
                __nv_bfloat16 h1 = __float2bfloat16_rn(p1);
                __nv_bfloat162 hp; hp.x = h0; hp.y = h1;
                memcpy(&pah[kc][q], &hp, 4);
                pal[kc][q] = pack2(p0 - __bfloat162float(h0), p1 - __bfloat162float(h1));
            }
        }

        {
            uint32_t vrow = lane & 15;
            uint32_t vcol = ((uint32_t)(lane >> 4) & 1) << 3;
#pragma unroll
            for (int kc = 0; kc < 2; kc++) {
#pragma unroll
                for (int dg = 0; dg < 4; dg++) {
                    uint32_t off = ((kc * 16 + vrow) * DSTR + dg * 16 + vcol) * 2;
                    uint32_t vfh[4], vfl[4];
                    ldsm4t(vfh, kb + 2 * ATILE + off);
                    ldsm4t(vfl, kb + 3 * ATILE + off);
                    uint32_t b0h[2] = {vfh[0], vfh[1]}, b1h[2] = {vfh[2], vfh[3]};
                    uint32_t b0l[2] = {vfl[0], vfl[1]}, b1l[2] = {vfl[2], vfl[3]};
                    mma16816(y[dg * 2],     pah[kc], b0h);
                    mma16816(y[dg * 2],     pah[kc], b0l);
                    mma16816(y[dg * 2],     pal[kc], b0h);
                    mma16816(y[dg * 2 + 1], pah[kc], b1h);
                    mma16816(y[dg * 2 + 1], pah[kc], b1l);
                    mma16816(y[dg * 2 + 1], pal[kc], b1h);
                }
            }
        }
        __syncthreads();
    }

    // ---- epilogue: y /= l -> bf16 hi/lo into g_yh/g_yl [b,n,c] ----
    const int bb = bh >> 4, hh = bh & 15;
    const float inv0 = 1.f / l0, inv1 = 1.f / l1;
    const int r0g = q0 + wid * 16 + (lane >> 2);
    size_t row0 = ((size_t)bb * Nseq + r0g) * Cdim + hh * Dh + (lane & 3) * 2;
    size_t row1 = row0 + (size_t)8 * Cdim;
#pragma unroll
    for (int dt = 0; dt < 8; dt++) {
        float v0 = y[dt][0] * inv0, v1 = y[dt][1] * inv0;
        float v2 = y[dt][2] * inv1, v3 = y[dt][3] * inv1;
        __nv_bfloat16 h0 = __float2bfloat16_rn(v0);
        __nv_bfloat16 h1 = __float2bfloat16_rn(v1);
        __nv_bfloat16 h2 = __float2bfloat16_rn(v2);
        __nv_bfloat16 h3 = __float2bfloat16_rn(v3);
        __nv_bfloat162 p01; p01.x = h0; p01.y = h1;
        __nv_bfloat162 p23; p23.x = h2; p23.y = h3;
        uint32_t u01, u23; memcpy(&u01, &p01, 4); memcpy(&u23, &p23, 4);
        *(uint32_t*)&g_yh[row0 + dt * 8] = u01;
        *(uint32_t*)&g_yh[row1 + dt * 8] = u23;
        *(uint32_t*)&g_yl[row0 + dt * 8] = pack2(v0 - __bfloat162float(h0),
                                                 v1 - __bfloat162float(h1));
        *(uint32_t*)&g_yl[row1 + dt * 8] = pack2(v2 - __bfloat162float(h2),
                                                 v3 - __bfloat162float(h3));
    }
}

// ---------------------------------------------------------------------------
extern "C" void kernel_launch(void* const* d_in, const int* in_sizes, int n_in,
                              void* d_out, int out_size)
{
    const float* x      = (const float*)d_in[0];   // [4,2048,1024]
    const float* w_attn = (const float*)d_in[1];   // [1024,3072]
    const float* w_proj = (const float*)d_in[2];   // [1024,1024]
    float* out = (float*)d_out;                    // [4,2048,1024]
    (void)in_sizes; (void)n_in; (void)out_size;

    // Dynamic-smem opt-in (idempotent host-side attribute; capture-safe).
    static bool attr_done = false;
    if (!attr_done) {
        cudaFuncSetAttribute(mma_gemm<0>, cudaFuncAttributeMaxDynamicSharedMemorySize, GSMEM);
        cudaFuncSetAttribute(mma_gemm<1>, cudaFuncAttributeMaxDynamicSharedMemorySize, GSMEM);
        attr_done = true;
    }

    // 0) Pre-passes: weight transpose+split, activation split
    split_transpose<0><<<dim3(3 * Cdim / 32, Cdim / 32), dim3(32, 8)>>>(w_attn, 3 * Cdim);
    split_transpose<1><<<dim3(Cdim / 32, Cdim / 32), dim3(32, 8)>>>(w_proj, Cdim);
    split_act<<<(Bz * Nseq * Cdim) / 1024, 256>>>(x);

    // 1) QKV projection -> bf16 hi/lo per-head layouts (q pre-scaled)
    mma_gemm<0><<<dim3(3 * Cdim / 128, (Bz * Nseq) / 128), 256, GSMEM>>>(nullptr);

    // 2) Flash attention (mma.sync, 128-q tiles) -> g_yh/g_yl bf16
    attn_mma<<<dim3(Nseq / 128, BHn), 256>>>();

    // 3) Output projection -> d_out (fp32)
    mma_gemm<1><<<dim3(Cdim / 128, (Bz * Nseq) / 128), 256, GSMEM>>>(out);
}